// round 2
// baseline (speedup 1.0000x reference)
#include <cuda_runtime.h>

#define L       48
#define BATCH   8192
#define EDIM    50
#define HDIM    512
#define VDIM    128
#define G4H     2048      // 4*HDIM
#define KPAD    576       // HDIM + EDIM padded to mult of 16
#define XOFF    512

// Scratch (allocation-free rule: __device__ globals)
__device__ float g_A[2][BATCH * KPAD];   // [h | x | zero-pad], ping-pong
__device__ float g_C[BATCH * HDIM];      // cell state
__device__ float g_Wc[G4H * KPAD];       // gate-interleaved combined weight
__device__ float g_bc[G4H];              // combined bias, gate-interleaved

__device__ __forceinline__ float fsig(float x) {
    return __fdividef(1.0f, 1.0f + __expf(-x));
}
__device__ __forceinline__ float ftanh_fast(float x) {
    float ax = fabsf(x);
    float e  = __expf(-2.0f * ax);
    float t  = __fdividef(1.0f - e, 1.0f + e);
    return copysignf(t, x);
}

// Build Wc[n][k] with n = 4*j + gate  (gate order i,f,g,o), cols [0,512)=W_hh, [512,562)=W_ih, rest 0
__global__ void prep_kernel(const float* __restrict__ W_ih, const float* __restrict__ W_hh,
                            const float* __restrict__ b_ih, const float* __restrict__ b_hh) {
    int idx = blockIdx.x * blockDim.x + threadIdx.x;
    if (idx >= G4H * KPAD) return;
    int n = idx / KPAD, k = idx - n * KPAD;
    int j = n >> 2, g = n & 3;
    int r = g * HDIM + j;               // original row in (4H, .) layout
    float v = 0.0f;
    if (k < HDIM)               v = W_hh[r * HDIM + k];
    else if (k < HDIM + EDIM)   v = W_ih[r * EDIM + (k - HDIM)];
    g_Wc[idx] = v;
    if (k == 0) g_bc[n] = b_ih[r] + b_hh[r];
}

__global__ void init_kernel(const float* __restrict__ h0, const float* __restrict__ c0) {
    int idx = blockIdx.x * blockDim.x + threadIdx.x;
    if (idx >= BATCH * HDIM) return;
    int b = idx >> 9, j = idx & (HDIM - 1);
    g_A[0][b * KPAD + j] = h0[idx];
    g_C[idx] = c0[idx];
}

// Gather x_t = emb[input[t]] into the x-columns of the current-parity A buffer
__global__ void xcopy_kernel(const int* __restrict__ input, const float* __restrict__ emb, int t) {
    int idx = blockIdx.x * blockDim.x + threadIdx.x;
    if (idx >= BATCH * EDIM) return;
    int b = idx / EDIM, e = idx - b * EDIM;
    int tok = input[t * BATCH + b];
    g_A[t & 1][b * KPAD + XOFF + e] = emb[tok * EDIM + e];
}

// gates = [h,x] @ Wc^T + bc ; fused LSTM cell update in epilogue.
// Reads g_A[t&1], writes h_{t+1} into g_A[(t+1)&1] and updates g_C.
__global__ __launch_bounds__(256, 2) void gates_kernel(int t) {
    const float* __restrict__ A  = g_A[t & 1];
    float* __restrict__       Hn = g_A[(t + 1) & 1];

    __shared__ float As[16][128];
    __shared__ float Bs[16][128];

    int tid = threadIdx.x;
    int tx = tid & 15, ty = tid >> 4;
    int brow = blockIdx.y << 7;
    int bcol = blockIdx.x << 7;

    int lr = tid >> 2;          // 0..63
    int lk = (tid & 3) << 2;    // 0,4,8,12

    const float* Ag = A    + (size_t)(brow + lr) * KPAD + lk;
    const float* Bg = g_Wc + (size_t)(bcol + lr) * KPAD + lk;

    float acc[8][8];
#pragma unroll
    for (int i = 0; i < 8; i++)
#pragma unroll
        for (int j = 0; j < 8; j++) acc[i][j] = 0.0f;

    for (int k0 = 0; k0 < KPAD; k0 += 16) {
        float4 a0 = *(const float4*)(Ag + k0);
        float4 a1 = *(const float4*)(Ag + (size_t)64 * KPAD + k0);
        float4 b0 = *(const float4*)(Bg + k0);
        float4 b1 = *(const float4*)(Bg + (size_t)64 * KPAD + k0);
        __syncthreads();
        As[lk + 0][lr] = a0.x; As[lk + 1][lr] = a0.y; As[lk + 2][lr] = a0.z; As[lk + 3][lr] = a0.w;
        As[lk + 0][lr + 64] = a1.x; As[lk + 1][lr + 64] = a1.y; As[lk + 2][lr + 64] = a1.z; As[lk + 3][lr + 64] = a1.w;
        Bs[lk + 0][lr] = b0.x; Bs[lk + 1][lr] = b0.y; Bs[lk + 2][lr] = b0.z; Bs[lk + 3][lr] = b0.w;
        Bs[lk + 0][lr + 64] = b1.x; Bs[lk + 1][lr + 64] = b1.y; Bs[lk + 2][lr + 64] = b1.z; Bs[lk + 3][lr + 64] = b1.w;
        __syncthreads();
#pragma unroll
        for (int kk = 0; kk < 16; kk++) {
            float4 af0 = *(const float4*)&As[kk][ty << 2];
            float4 af1 = *(const float4*)&As[kk][64 + (ty << 2)];
            float4 bf0 = *(const float4*)&Bs[kk][tx << 2];
            float4 bf1 = *(const float4*)&Bs[kk][64 + (tx << 2)];
            float ar[8] = {af0.x, af0.y, af0.z, af0.w, af1.x, af1.y, af1.z, af1.w};
            float br[8] = {bf0.x, bf0.y, bf0.z, bf0.w, bf1.x, bf1.y, bf1.z, bf1.w};
#pragma unroll
            for (int i = 0; i < 8; i++)
#pragma unroll
                for (int j = 0; j < 8; j++)
                    acc[i][j] += ar[i] * br[j];
        }
    }

    // bias (depends only on column, load once)
    float bcv[8];
#pragma unroll
    for (int c = 0; c < 4; c++) {
        bcv[c]     = g_bc[bcol + (tx << 2) + c];
        bcv[4 + c] = g_bc[bcol + 64 + (tx << 2) + c];
    }

    // fused LSTM cell epilogue: each 4-col fragment = (i,f,g,o) of one hidden unit
#pragma unroll
    for (int i = 0; i < 8; i++) {
        int row = brow + ((i < 4) ? ((ty << 2) + i) : (64 + (ty << 2) + i - 4));
#pragma unroll
        for (int cg = 0; cg < 2; cg++) {
            int nb = bcol + cg * 64 + (tx << 2);
            int j  = nb >> 2;                       // hidden unit index
            float gi = acc[i][cg * 4 + 0] + bcv[cg * 4 + 0];
            float gf = acc[i][cg * 4 + 1] + bcv[cg * 4 + 1];
            float gg = acc[i][cg * 4 + 2] + bcv[cg * 4 + 2];
            float go = acc[i][cg * 4 + 3] + bcv[cg * 4 + 3];
            float cold = g_C[row * HDIM + j];
            float cn = fsig(gf) * cold + fsig(gi) * ftanh_fast(gg);
            g_C[row * HDIM + j] = cn;
            Hn[(size_t)row * KPAD + j] = fsig(go) * ftanh_fast(cn);
        }
    }
}

// scores_t = h_t @ W_out^T + b_out  (M=8192, N=128, K=512). 64-row tiles, 128 blocks.
__global__ __launch_bounds__(256) void out_kernel(int t, const float* __restrict__ Wout,
                                                  const float* __restrict__ bout,
                                                  float* __restrict__ out) {
    const float* __restrict__ A = g_A[(t + 1) & 1];   // holds h_t

    __shared__ float As[16][64];
    __shared__ float Bs[16][128];

    int tid = threadIdx.x;
    int tx = tid & 15, ty = tid >> 4;
    int brow = blockIdx.y << 6;

    int lr = tid >> 2;          // 0..63
    int lk = (tid & 3) << 2;

    float acc[4][8];
#pragma unroll
    for (int i = 0; i < 4; i++)
#pragma unroll
        for (int j = 0; j < 8; j++) acc[i][j] = 0.0f;

    for (int k0 = 0; k0 < HDIM; k0 += 16) {
        float4 a0 = *(const float4*)(A + (size_t)(brow + lr) * KPAD + k0 + lk);
        float4 b0 = *(const float4*)(Wout + (size_t)lr * HDIM + k0 + lk);
        float4 b1 = *(const float4*)(Wout + (size_t)(lr + 64) * HDIM + k0 + lk);
        __syncthreads();
        As[lk + 0][lr] = a0.x; As[lk + 1][lr] = a0.y; As[lk + 2][lr] = a0.z; As[lk + 3][lr] = a0.w;
        Bs[lk + 0][lr] = b0.x; Bs[lk + 1][lr] = b0.y; Bs[lk + 2][lr] = b0.z; Bs[lk + 3][lr] = b0.w;
        Bs[lk + 0][lr + 64] = b1.x; Bs[lk + 1][lr + 64] = b1.y; Bs[lk + 2][lr + 64] = b1.z; Bs[lk + 3][lr + 64] = b1.w;
        __syncthreads();
#pragma unroll
        for (int kk = 0; kk < 16; kk++) {
            float4 af  = *(const float4*)&As[kk][ty << 2];
            float4 bf0 = *(const float4*)&Bs[kk][tx << 2];
            float4 bf1 = *(const float4*)&Bs[kk][64 + (tx << 2)];
            float ar[4] = {af.x, af.y, af.z, af.w};
            float br[8] = {bf0.x, bf0.y, bf0.z, bf0.w, bf1.x, bf1.y, bf1.z, bf1.w};
#pragma unroll
            for (int i = 0; i < 4; i++)
#pragma unroll
                for (int j = 0; j < 8; j++)
                    acc[i][j] += ar[i] * br[j];
        }
    }

    float* dst = out + (size_t)t * BATCH * VDIM;
#pragma unroll
    for (int i = 0; i < 4; i++) {
        int row = brow + (ty << 2) + i;
#pragma unroll
        for (int cg = 0; cg < 2; cg++) {
            int nb = cg * 64 + (tx << 2);
            float4 v;
            v.x = acc[i][cg * 4 + 0] + bout[nb + 0];
            v.y = acc[i][cg * 4 + 1] + bout[nb + 1];
            v.z = acc[i][cg * 4 + 2] + bout[nb + 2];
            v.w = acc[i][cg * 4 + 3] + bout[nb + 3];
            *(float4*)(dst + (size_t)row * VDIM + nb) = v;
        }
    }
}

// hT, cT tail (h_47 lives in g_A[0] since 48 is even)
__global__ void final_kernel(float* __restrict__ out) {
    int idx = blockIdx.x * blockDim.x + threadIdx.x;
    if (idx >= BATCH * HDIM) return;
    int b = idx >> 9, j = idx & (HDIM - 1);
    size_t base = (size_t)L * BATCH * VDIM;
    out[base + idx] = g_A[0][(size_t)b * KPAD + j];
    out[base + (size_t)BATCH * HDIM + idx] = g_C[idx];
}

extern "C" void kernel_launch(void* const* d_in, const int* in_sizes, int n_in,
                              void* d_out, int out_size) {
    const int*   input = (const int*)d_in[0];
    const float* h0    = (const float*)d_in[1];
    const float* c0    = (const float*)d_in[2];
    const float* emb   = (const float*)d_in[3];
    const float* W_ih  = (const float*)d_in[4];
    const float* W_hh  = (const float*)d_in[5];
    const float* b_ih  = (const float*)d_in[6];
    const float* b_hh  = (const float*)d_in[7];
    const float* W_out = (const float*)d_in[8];
    const float* b_out = (const float*)d_in[9];
    float* out = (float*)d_out;

    prep_kernel<<<(G4H * KPAD + 255) / 256, 256>>>(W_ih, W_hh, b_ih, b_hh);
    init_kernel<<<(BATCH * HDIM + 255) / 256, 256>>>(h0, c0);

    dim3 ggrid(G4H / 128, BATCH / 128);
    dim3 ogrid(1, BATCH / 64);
    for (int t = 0; t < L; t++) {
        xcopy_kernel<<<(BATCH * EDIM + 255) / 256, 256>>>(input, emb, t);
        gates_kernel<<<ggrid, 256>>>(t);
        out_kernel<<<ogrid, 256>>>(t, W_out, b_out, out);
    }
    final_kernel<<<(BATCH * HDIM + 255) / 256, 256>>>(out);
}

// round 14
// speedup vs baseline: 1.7124x; 1.7124x over previous
#include <cuda_runtime.h>
#include <cuda_bf16.h>

#define L      48
#define BATCH  8192
#define EDIM   50
#define HDIM   512
#define VDIM   128
#define G4H    2048
#define KSEG   576         // padded K per segment (512 h + 50 x + 14 pad)
#define AW     1152        // A row width: [hi(576) | lo(576)]
#define WW     1728        // Wext row width: [W_hi | W_lo | W_hi]
#define WOW    1536        // Woext row width: [Wo_hi | Wo_lo | Wo_hi]

// ---------------- device scratch (allocation-free rule) ----------------
__device__ __nv_bfloat16 g_Abf[2][(size_t)BATCH * AW];   // ping-pong [h|x] hi/lo
__device__ __nv_bfloat16 g_Wext[(size_t)G4H * WW];       // gate-interleaved split weight
__device__ __nv_bfloat16 g_Woext[(size_t)VDIM * WOW];    // split output weight
__device__ float g_C[(size_t)BATCH * HDIM];              // cell state fp32
__device__ float g_bc[G4H];                              // fused bias, gate-interleaved

// ---------------- helpers ----------------
__device__ __forceinline__ unsigned smem_u32(const void* p) {
    unsigned a;
    asm("{ .reg .u64 t; cvta.to.shared.u64 t, %1; cvt.u32.u64 %0, t; }" : "=r"(a) : "l"(p));
    return a;
}
__device__ __forceinline__ void cp_async16(unsigned dst, const void* src) {
    asm volatile("cp.async.cg.shared.global [%0], [%1], 16;" :: "r"(dst), "l"(src));
}
__device__ __forceinline__ void cp_commit() { asm volatile("cp.async.commit_group;" ::: "memory"); }
template <int N> __device__ __forceinline__ void cp_wait() {
    asm volatile("cp.async.wait_group %0;" :: "n"(N) : "memory");
}
__device__ __forceinline__ void ldsm4(unsigned& r0, unsigned& r1, unsigned& r2, unsigned& r3,
                                      unsigned addr) {
    asm volatile("ldmatrix.sync.aligned.m8n8.x4.shared.b16 {%0,%1,%2,%3}, [%4];"
                 : "=r"(r0), "=r"(r1), "=r"(r2), "=r"(r3) : "r"(addr));
}
__device__ __forceinline__ void mma16816(float& c0, float& c1, float& c2, float& c3,
                                         unsigned a0, unsigned a1, unsigned a2, unsigned a3,
                                         unsigned b0, unsigned b1) {
    asm volatile("mma.sync.aligned.m16n8k16.row.col.f32.bf16.bf16.f32 "
        "{%0,%1,%2,%3}, {%4,%5,%6,%7}, {%8,%9}, {%0,%1,%2,%3};"
        : "+f"(c0), "+f"(c1), "+f"(c2), "+f"(c3)
        : "r"(a0), "r"(a1), "r"(a2), "r"(a3), "r"(b0), "r"(b1));
}
__device__ __forceinline__ float fsig(float x) {
    return __fdividef(1.0f, 1.0f + __expf(-x));
}
__device__ __forceinline__ float ftanh_fast(float x) {
    float ax = fabsf(x);
    float e  = __expf(-2.0f * ax);
    float t  = __fdividef(1.0f - e, 1.0f + e);
    return copysignf(t, x);
}
__device__ __forceinline__ void split_bf16(float x, __nv_bfloat16& hi, __nv_bfloat16& lo) {
    hi = __float2bfloat16_rn(x);
    lo = __float2bfloat16_rn(x - __bfloat162float(hi));
}

// ---------------- prep kernels (one-time) ----------------
__global__ void prep_w_kernel(const float* __restrict__ W_ih, const float* __restrict__ W_hh) {
    long long idx = (long long)blockIdx.x * blockDim.x + threadIdx.x;
    if (idx >= (long long)G4H * WW) return;
    int n = (int)(idx / WW), k = (int)(idx - (long long)n * WW);
    int seg = k / KSEG, kk = k - seg * KSEG;
    int j = n >> 2, g = n & 3;
    int r = g * HDIM + j;
    float w = 0.0f;
    if (kk < HDIM)            w = W_hh[(size_t)r * HDIM + kk];
    else if (kk < HDIM+EDIM)  w = W_ih[(size_t)r * EDIM + (kk - HDIM)];
    __nv_bfloat16 hi, lo; split_bf16(w, hi, lo);
    g_Wext[idx] = (seg == 1) ? lo : hi;
}
__global__ void prep_wo_kernel(const float* __restrict__ W_out) {
    int idx = blockIdx.x * blockDim.x + threadIdx.x;
    if (idx >= VDIM * WOW) return;
    int n = idx / WOW, k = idx - n * WOW;
    int seg = k / HDIM, kk = k - seg * HDIM;
    float w = W_out[(size_t)n * HDIM + kk];
    __nv_bfloat16 hi, lo; split_bf16(w, hi, lo);
    g_Woext[idx] = (seg == 1) ? lo : hi;
}
__global__ void prep_bc_kernel(const float* __restrict__ b_ih, const float* __restrict__ b_hh) {
    int n = blockIdx.x * blockDim.x + threadIdx.x;
    if (n >= G4H) return;
    int j = n >> 2, g = n & 3, r = g * HDIM + j;
    g_bc[n] = b_ih[r] + b_hh[r];
}
__global__ void init_kernel(const float* __restrict__ h0, const float* __restrict__ c0) {
    int idx = blockIdx.x * blockDim.x + threadIdx.x;
    if (idx >= BATCH * HDIM) return;
    int b = idx >> 9, j = idx & (HDIM - 1);
    __nv_bfloat16 hi, lo; split_bf16(h0[idx], hi, lo);
    g_Abf[0][(size_t)b * AW + j] = hi;
    g_Abf[0][(size_t)b * AW + KSEG + j] = lo;
    g_C[idx] = c0[idx];
}
__global__ void xcopy_kernel(const int* __restrict__ input, const float* __restrict__ emb, int t) {
    int idx = blockIdx.x * blockDim.x + threadIdx.x;
    if (idx >= BATCH * EDIM) return;
    int b = idx / EDIM, e = idx - b * EDIM;
    int tok = input[(size_t)t * BATCH + b];
    __nv_bfloat16 hi, lo; split_bf16(emb[(size_t)tok * EDIM + e], hi, lo);
    g_Abf[t & 1][(size_t)b * AW + HDIM + e] = hi;
    g_Abf[t & 1][(size_t)b * AW + KSEG + HDIM + e] = lo;
}

// ---------------- gates MMA kernel (warp-level mma.sync, bf16) ----------------
// CTA tile 128x128, K-tile 32, 3-stage cp.async pipeline.
// SMEM rows padded to 40 bf16 (80B) for conflict-free ldmatrix.
// Stages: A 3x128x80B = 30720, B same. Epilogue reuses smem: gates fp32 [128][132] = 67584B.
#define G_TILES    54            // 1728/32
#define GPITCH     40            // bf16 elems per smem row
#define GA_ST      10240         // 128*80
#define GS_SMEM    67584
#define GEPI_P     132           // gates smem pitch (floats)

__device__ __forceinline__ void gates_fill(unsigned sb, int tid, int brow, int bcol,
                                           const __nv_bfloat16* Abuf, int stage, int tile) {
    const int p = tile / 18, kk = tile - p * 18;
    const int acol = ((p == 2) ? KSEG : 0) + kk * 32;
    const int wcol = p * KSEG + kk * 32;
    const unsigned aBase = sb + stage * GA_ST;
    const unsigned bBase = sb + 30720u + stage * GA_ST;
#pragma unroll
    for (int i = 0; i < 4; i++) {
        int cid = tid + (i << 8);            // 0..1023
        int ch = cid & 3;                    // 16B chunk (8 bf16)
        if (cid < 512) {
            int r = cid >> 2;                // 0..127
            cp_async16(aBase + r * 80 + ch * 16,
                       Abuf + (size_t)(brow + r) * AW + acol + ch * 8);
        } else {
            int r = (cid - 512) >> 2;
            cp_async16(bBase + r * 80 + ch * 16,
                       g_Wext + (size_t)(bcol + r) * WW + wcol + ch * 8);
        }
    }
    cp_commit();
}

__global__ void __launch_bounds__(256, 2) gates_mma_kernel(int par) {
    extern __shared__ char smem[];
    const unsigned sb = smem_u32(smem);
    const int tid = threadIdx.x, wid = tid >> 5, lane = tid & 31;
    const int warp_m = wid >> 2, warp_n = wid & 3;     // 2x4 warp grid, warp tile 64x32
    const int bcol = blockIdx.x << 7;                  // gate cols
    const int brow = blockIdx.y << 7;                  // batch rows
    const __nv_bfloat16* Abuf = g_Abf[par];
    __nv_bfloat16* Anext = g_Abf[par ^ 1];

    float acc[4][4][4];
#pragma unroll
    for (int i = 0; i < 4; i++)
#pragma unroll
        for (int j = 0; j < 4; j++)
#pragma unroll
            for (int q = 0; q < 4; q++) acc[i][j][q] = 0.0f;

    gates_fill(sb, tid, brow, bcol, Abuf, 0, 0);
    gates_fill(sb, tid, brow, bcol, Abuf, 1, 1);

    const int lrow = lane & 15;
    const int lkb  = (lane >> 4) * 16;     // byte offset of k-half (8 bf16)

    for (int t = 0; t < G_TILES; t++) {
        if (t == G_TILES - 1) cp_wait<0>(); else cp_wait<1>();
        __syncthreads();
        int f = t + 2;
        if (f < G_TILES) gates_fill(sb, tid, brow, bcol, Abuf, f % 3, f);

        const int s = t % 3;
        const unsigned aBase = sb + s * GA_ST;
        const unsigned bBase = sb + 30720u + s * GA_ST;
#pragma unroll
        for (int ks = 0; ks < 2; ks++) {
            const unsigned koff = ks * 32 + lkb;       // bytes within 80B row
            unsigned a[4][4], b[2][4];
#pragma unroll
            for (int mt = 0; mt < 4; mt++)
                ldsm4(a[mt][0], a[mt][1], a[mt][2], a[mt][3],
                      aBase + (warp_m * 64 + mt * 16 + lrow) * 80 + koff);
#pragma unroll
            for (int bt = 0; bt < 2; bt++)
                ldsm4(b[bt][0], b[bt][1], b[bt][2], b[bt][3],
                      bBase + (warp_n * 32 + bt * 16 + lrow) * 80 + koff);
#pragma unroll
            for (int mt = 0; mt < 4; mt++)
#pragma unroll
                for (int nt = 0; nt < 4; nt++) {
                    int bt = nt >> 1, sel = nt & 1;
                    mma16816(acc[mt][nt][0], acc[mt][nt][1], acc[mt][nt][2], acc[mt][nt][3],
                             a[mt][0], a[mt][1], a[mt][2], a[mt][3],
                             b[bt][sel], b[bt][sel + 2]);
                }
        }
    }

    // stash gates to smem (reuse pipeline smem), then fused LSTM epilogue
    __syncthreads();
    float* gsm = (float*)smem;
    const int row0 = lane >> 2, colq = (lane & 3) * 2;
#pragma unroll
    for (int mt = 0; mt < 4; mt++)
#pragma unroll
        for (int nt = 0; nt < 4; nt++) {
            int rs = warp_m * 64 + mt * 16 + row0;
            int cs = warp_n * 32 + nt * 8 + colq;
            *(float2*)&gsm[rs * GEPI_P + cs]       = make_float2(acc[mt][nt][0], acc[mt][nt][1]);
            *(float2*)&gsm[(rs + 8) * GEPI_P + cs] = make_float2(acc[mt][nt][2], acc[mt][nt][3]);
        }
    __syncthreads();

    {
        const int r = tid >> 1, half = tid & 1;
        const int grow = brow + r;
        const float* gr = gsm + r * GEPI_P + half * 64;
        const float* bcp = g_bc + bcol + half * 64;
        const int jbase = (bcol >> 2) + half * 16;
        float* cptr = g_C + (size_t)grow * HDIM + jbase;
        float cv[16];
#pragma unroll
        for (int q = 0; q < 4; q++) *(float4*)&cv[4 * q] = *(const float4*)&cptr[4 * q];
        union { __nv_bfloat16 b[16]; uint4 v[2]; } Hh, Hl;
#pragma unroll
        for (int jj = 0; jj < 16; jj++) {
            float gi = fsig(gr[4 * jj + 0] + bcp[4 * jj + 0]);
            float gf = fsig(gr[4 * jj + 1] + bcp[4 * jj + 1]);
            float gg = ftanh_fast(gr[4 * jj + 2] + bcp[4 * jj + 2]);
            float go = fsig(gr[4 * jj + 3] + bcp[4 * jj + 3]);
            float cn = gf * cv[jj] + gi * gg;
            cv[jj] = cn;
            float h = go * ftanh_fast(cn);
            split_bf16(h, Hh.b[jj], Hl.b[jj]);
        }
#pragma unroll
        for (int q = 0; q < 4; q++) *(float4*)&cptr[4 * q] = *(const float4*)&cv[4 * q];
        *(uint4*)&Anext[(size_t)grow * AW + jbase]            = Hh.v[0];
        *(uint4*)&Anext[(size_t)grow * AW + jbase + 8]        = Hh.v[1];
        *(uint4*)&Anext[(size_t)grow * AW + KSEG + jbase]     = Hl.v[0];
        *(uint4*)&Anext[(size_t)grow * AW + KSEG + jbase + 8] = Hl.v[1];
    }
}

// ---------------- output projection MMA kernel ----------------
// CTA tile 64x128 (N=V=128), K-tile 32, 3 stages. Grid = BATCH/64 = 128.
#define O_TILES    48            // 1536/32
#define OA_ST      5120          // 64*80
#define OB_ST      10240         // 128*80
#define OS_SMEM    46080         // 3*(5120+10240)

__device__ __forceinline__ void out_fill(unsigned sb, int tid, int brow,
                                         const __nv_bfloat16* Abuf, int stage, int tile) {
    const int p = tile / 16, kk = tile - p * 16;
    const int acol = ((p == 2) ? KSEG : 0) + kk * 32;
    const int wcol = p * HDIM + kk * 32;
    const unsigned aBase = sb + stage * OA_ST;
    const unsigned bBase = sb + 15360u + stage * OB_ST;
#pragma unroll
    for (int i = 0; i < 3; i++) {
        int cid = tid + (i << 8);            // 0..767
        int ch = cid & 3;
        if (cid < 256) {
            int r = cid >> 2;                // 0..63
            cp_async16(aBase + r * 80 + ch * 16,
                       Abuf + (size_t)(brow + r) * AW + acol + ch * 8);
        } else {
            int r = (cid - 256) >> 2;        // 0..127
            cp_async16(bBase + r * 80 + ch * 16,
                       g_Woext + (size_t)r * WOW + wcol + ch * 8);
        }
    }
    cp_commit();
}

__global__ void __launch_bounds__(256, 2) out_mma_kernel(int step, int par,
                                                         const float* __restrict__ bout,
                                                         float* __restrict__ out) {
    extern __shared__ char smem[];
    const unsigned sb = smem_u32(smem);
    const int tid = threadIdx.x, wid = tid >> 5, lane = tid & 31;
    const int warp_m = wid >> 2, warp_n = wid & 3;     // warp tile 32x32
    const int brow = blockIdx.x << 6;
    const __nv_bfloat16* Abuf = g_Abf[par];

    float acc[2][4][4];
#pragma unroll
    for (int i = 0; i < 2; i++)
#pragma unroll
        for (int j = 0; j < 4; j++)
#pragma unroll
            for (int q = 0; q < 4; q++) acc[i][j][q] = 0.0f;

    out_fill(sb, tid, brow, Abuf, 0, 0);
    out_fill(sb, tid, brow, Abuf, 1, 1);

    const int lrow = lane & 15;
    const int lkb  = (lane >> 4) * 16;

    for (int t = 0; t < O_TILES; t++) {
        if (t == O_TILES - 1) cp_wait<0>(); else cp_wait<1>();
        __syncthreads();
        int f = t + 2;
        if (f < O_TILES) out_fill(sb, tid, brow, Abuf, f % 3, f);

        const int s = t % 3;
        const unsigned aBase = sb + s * OA_ST;
        const unsigned bBase = sb + 15360u + s * OB_ST;
#pragma unroll
        for (int ks = 0; ks < 2; ks++) {
            const unsigned koff = ks * 32 + lkb;
            unsigned a[2][4], b[2][4];
#pragma unroll
            for (int mt = 0; mt < 2; mt++)
                ldsm4(a[mt][0], a[mt][1], a[mt][2], a[mt][3],
                      aBase + (warp_m * 32 + mt * 16 + lrow) * 80 + koff);
#pragma unroll
            for (int bt = 0; bt < 2; bt++)
                ldsm4(b[bt][0], b[bt][1], b[bt][2], b[bt][3],
                      bBase + (warp_n * 32 + bt * 16 + lrow) * 80 + koff);
#pragma unroll
            for (int mt = 0; mt < 2; mt++)
#pragma unroll
                for (int nt = 0; nt < 4; nt++) {
                    int bt = nt >> 1, sel = nt & 1;
                    mma16816(acc[mt][nt][0], acc[mt][nt][1], acc[mt][nt][2], acc[mt][nt][3],
                             a[mt][0], a[mt][1], a[mt][2], a[mt][3],
                             b[bt][sel], b[bt][sel + 2]);
                }
        }
    }

    // direct epilogue: bias + store
    const int row0 = lane >> 2, colq = (lane & 3) * 2;
    float* dstbase = out + (size_t)step * BATCH * VDIM;
#pragma unroll
    for (int mt = 0; mt < 2; mt++)
#pragma unroll
        for (int nt = 0; nt < 4; nt++) {
            int rs = brow + warp_m * 32 + mt * 16 + row0;
            int cs = warp_n * 32 + nt * 8 + colq;
            float2 bv = *(const float2*)&bout[cs];
            *(float2*)&dstbase[(size_t)rs * VDIM + cs] =
                make_float2(acc[mt][nt][0] + bv.x, acc[mt][nt][1] + bv.y);
            *(float2*)&dstbase[(size_t)(rs + 8) * VDIM + cs] =
                make_float2(acc[mt][nt][2] + bv.x, acc[mt][nt][3] + bv.y);
        }
}

// ---------------- tail: hT, cT ----------------
__global__ void final_kernel(float* __restrict__ out) {
    int idx = blockIdx.x * blockDim.x + threadIdx.x;
    if (idx >= BATCH * HDIM) return;
    int b = idx >> 9, j = idx & (HDIM - 1);
    size_t base = (size_t)L * BATCH * VDIM;
    float h = __bfloat162float(g_Abf[0][(size_t)b * AW + j]) +
              __bfloat162float(g_Abf[0][(size_t)b * AW + KSEG + j]);
    out[base + idx] = h;
    out[base + (size_t)BATCH * HDIM + idx] = g_C[idx];
}

// ---------------- launch ----------------
extern "C" void kernel_launch(void* const* d_in, const int* in_sizes, int n_in,
                              void* d_out, int out_size) {
    const int*   input = (const int*)d_in[0];
    const float* h0    = (const float*)d_in[1];
    const float* c0    = (const float*)d_in[2];
    const float* emb   = (const float*)d_in[3];
    const float* W_ih  = (const float*)d_in[4];
    const float* W_hh  = (const float*)d_in[5];
    const float* b_ih  = (const float*)d_in[6];
    const float* b_hh  = (const float*)d_in[7];
    const float* W_out = (const float*)d_in[8];
    const float* b_out = (const float*)d_in[9];
    float* out = (float*)d_out;

    cudaFuncSetAttribute(gates_mma_kernel, cudaFuncAttributeMaxDynamicSharedMemorySize, GS_SMEM);
    cudaFuncSetAttribute(out_mma_kernel,   cudaFuncAttributeMaxDynamicSharedMemorySize, OS_SMEM);

    long long wtot = (long long)G4H * WW;
    prep_w_kernel<<<(unsigned)((wtot + 255) / 256), 256>>>(W_ih, W_hh);
    prep_wo_kernel<<<(VDIM * WOW + 255) / 256, 256>>>(W_out);
    prep_bc_kernel<<<(G4H + 255) / 256, 256>>>(b_ih, b_hh);
    init_kernel<<<(BATCH * HDIM + 255) / 256, 256>>>(h0, c0);

    dim3 ggrid(G4H / 128, BATCH / 128);     // (16, 64)
    for (int t = 0; t < L; t++) {
        xcopy_kernel<<<(BATCH * EDIM + 255) / 256, 256>>>(input, emb, t);
        gates_mma_kernel<<<ggrid, 256, GS_SMEM>>>(t & 1);
        out_mma_kernel<<<BATCH / 64, 256, OS_SMEM>>>(t, (t + 1) & 1, b_out, out);
    }
    final_kernel<<<(BATCH * HDIM + 255) / 256, 256>>>(out);
}